// round 7
// baseline (speedup 1.0000x reference)
#include <cuda_runtime.h>
#include <math.h>

#define THREADS 256
#define MAXN 4096
#define NB1 1024        // first-pass bins (top 10 bits of key)
#define SH1 22          // 32 - 10

// Order-preserving float->uint key: monotonic increasing with float value.
__device__ __forceinline__ unsigned f2key(float v) {
    unsigned u = __float_as_uint(v);
    return u ^ (unsigned)(((int)u >> 31) | 0x80000000u);
}
__device__ __forceinline__ float key2f(unsigned key) {
    unsigned u = (key & 0x80000000u) ? (key ^ 0x80000000u) : ~key;
    return __uint_as_float(u);
}

// Warp-aggregated histogram increment: one conflict-free atomic per distinct
// bin per warp (all 32 lanes must be active).
__device__ __forceinline__ void hist_inc_agg(unsigned* hist, unsigned d, int lane) {
    unsigned same = __match_any_sync(0xFFFFFFFFu, d);
    if ((__ffs(same) - 1) == lane)
        atomicAdd(&hist[d], __popc(same));
}

// Warp-collective: find bin containing the krem-th element (DESC = count from
// top bin downward, else from bottom upward). Returns bin index + residual rank.
template<int NB, bool DESC>
__device__ __forceinline__ void resolve(const unsigned* __restrict__ hist, int krem,
                                        int lane, unsigned &bin, int &krem_out)
{
    constexpr int BPL = NB / 32;
    unsigned s = 0;
    #pragma unroll
    for (int j = 0; j < BPL; j++) {
        int b = DESC ? (NB - 1 - (lane * BPL + j)) : (lane * BPL + j);
        s += hist[b];
    }
    unsigned p = s;
    #pragma unroll
    for (int o = 1; o < 32; o <<= 1) {
        unsigned t = __shfl_up_sync(0xFFFFFFFFu, p, o);
        if (lane >= o) p += t;
    }
    unsigned excl = p - s;
    bool cross = (excl < (unsigned)krem) && (p >= (unsigned)krem);
    unsigned m = __ballot_sync(0xFFFFFFFFu, cross);
    int src = __ffs(m) - 1;
    unsigned bsel = 0; int k2 = 0;
    if (lane == src) {
        unsigned cum = excl;
        #pragma unroll
        for (int j = 0; j < BPL; j++) {
            int b = DESC ? (NB - 1 - (lane * BPL + j)) : (lane * BPL + j);
            unsigned c = hist[b];
            if (cum + c >= (unsigned)krem) { bsel = (unsigned)b; k2 = krem - (int)cum; break; }
            cum += c;
        }
    }
    bin = __shfl_sync(0xFFFFFFFFu, bsel, src);
    krem_out = __shfl_sync(0xFFFFFFFFu, k2, src);
}

__global__ void __launch_bounds__(THREADS, 8)
wildcat_kernel(const float* __restrict__ x, float* __restrict__ out,
               int n, int kmax, int kmin, float alpha)
{
    __shared__ float    s_val[MAXN];     // candidate VALUES: H grows from 0, L from MAXN-1
    __shared__ unsigned s_hist[NB1];     // L0: 1024 bins; sublevels: [0:256)=H, [256:512)=L
    __shared__ unsigned s_selH, s_selL;
    __shared__ int      s_kremH, s_kremL;
    __shared__ int      s_cntH, s_cntL;
    __shared__ float    s_red[2][THREADS / 32];

    const int tid  = threadIdx.x;
    const int lane = tid & 31;
    const int wid  = tid >> 5;
    const long long row = blockIdx.x;
    const float* __restrict__ xr = x + row * (long long)n;

    // ---- init ----
    ((uint4*)s_hist)[tid] = make_uint4(0, 0, 0, 0);   // clears all 1024 bins
    if (tid == 0) { s_cntH = 0; s_cntL = 0; }
    __syncthreads();

    const int n4 = n >> 2;
    const float4* __restrict__ xr4 = (const float4*)xr;
    const int nv4 = (n4 / THREADS) * THREADS;

    // ===== pass 1: gmem read + 10-bit histogram, warp-aggregated atomics ======
    for (int i = tid; i < nv4; i += THREADS) {
        float4 v = xr4[i];
        hist_inc_agg(s_hist, f2key(v.x) >> SH1, lane);
        hist_inc_agg(s_hist, f2key(v.y) >> SH1, lane);
        hist_inc_agg(s_hist, f2key(v.z) >> SH1, lane);
        hist_inc_agg(s_hist, f2key(v.w) >> SH1, lane);
    }
    for (int i = nv4 * 4 + tid; i < n; i += THREADS) {   // tail (none for n=4096)
        atomicAdd(&s_hist[f2key(xr[i]) >> SH1], 1u);
    }
    __syncthreads();

    // ---- resolve level 0 (two warps in parallel) ----
    if (wid == 0) {
        unsigned b; int k2;
        resolve<NB1, true>(s_hist, kmax, lane, b, k2);
        if (lane == 0) { s_selH = b; s_kremH = k2; }
    } else if (wid == 1) {
        unsigned b; int k2;
        resolve<NB1, false>(s_hist, kmin, lane, b, k2);
        if (lane == 0) { s_selL = b; s_kremL = k2; }
    }
    __syncthreads();

    const unsigned binH = s_selH;
    const unsigned binL = s_selL;
    const bool sameBin = (binH == binL);

    // clear the 512 sublevel bins
    s_hist[tid] = 0;
    s_hist[tid + 256] = 0;
    __syncthreads();

    // ===== pass 2: gmem re-read (L2/L1 hit): bulk sums + aggregated compaction =
    //        + inline next-level (bits 21..14) histogram for candidates.
    float sumT = 0.0f, sumB = 0.0f;
    for (int i = tid; i < nv4; i += THREADS) {
        float4 v = xr4[i];
        #pragma unroll
        for (int j = 0; j < 4; j++) {
            float f = (j == 0) ? v.x : (j == 1) ? v.y : (j == 2) ? v.z : v.w;
            unsigned key = f2key(f);
            unsigned b = key >> SH1;
            if (b > binH) sumT += f;
            if (b < binL) sumB += f;

            // aggregated append to H list
            unsigned bmH = __ballot_sync(0xFFFFFFFFu, b == binH);
            if (b == binH) {
                int leader = __ffs(bmH) - 1;
                int base;
                if (lane == leader) base = atomicAdd(&s_cntH, __popc(bmH));
                base = __shfl_sync(bmH, base, leader);
                s_val[base + __popc(bmH & ((1u << lane) - 1u))] = f;
                atomicAdd(&s_hist[(key >> 14) & 0xFFu], 1u);
            }
            if (!sameBin) {
                unsigned bmL = __ballot_sync(0xFFFFFFFFu, b == binL);
                if (b == binL) {
                    int leader = __ffs(bmL) - 1;
                    int base;
                    if (lane == leader) base = atomicAdd(&s_cntL, __popc(bmL));
                    base = __shfl_sync(bmL, base, leader);
                    s_val[MAXN - 1 - (base + __popc(bmL & ((1u << lane) - 1u)))] = f;
                    atomicAdd(&s_hist[256 + ((key >> 14) & 0xFFu)], 1u);
                }
            }
        }
    }
    for (int i = nv4 * 4 + tid; i < n; i += THREADS) {   // tail
        float f = xr[i];
        unsigned key = f2key(f);
        unsigned b = key >> SH1;
        if (b > binH) sumT += f;
        if (b < binL) sumB += f;
        if (b == binH) {
            int p = atomicAdd(&s_cntH, 1);
            s_val[p] = f;
            atomicAdd(&s_hist[(key >> 14) & 0xFFu], 1u);
        } else if (b == binL) {
            int p = atomicAdd(&s_cntL, 1);
            s_val[MAXN - 1 - p] = f;
            atomicAdd(&s_hist[256 + ((key >> 14) & 0xFFu)], 1u);
        }
    }
    __syncthreads();

    const int cntH = s_cntH;
    const int cntL = sameBin ? cntH : s_cntL;

    // ---- resolve level 1 (bits 21..14) ----
    if (wid == 0) {
        unsigned b; int k2;
        resolve<256, true>(s_hist, s_kremH, lane, b, k2);
        if (lane == 0) { s_selH = (binH << 8) | b; s_kremH = k2; }
    } else if (wid == 1) {
        unsigned b; int k2;
        resolve<256, false>(sameBin ? s_hist : (s_hist + 256), s_kremL, lane, b, k2);
        if (lane == 0) { s_selL = (binL << 8) | b; s_kremL = k2; }
    }
    __syncthreads();

    // ===== level 2 (bits 13..6) over candidate values ==========================
    {
        const unsigned pH = s_selH;
        const unsigned pL = s_selL;
        s_hist[tid] = 0;
        s_hist[tid + 256] = 0;
        __syncthreads();
        for (int t = tid; t < cntH; t += THREADS) {
            unsigned key = f2key(s_val[t]);
            if ((key >> 14) == pH) atomicAdd(&s_hist[(key >> 6) & 0xFFu], 1u);
        }
        for (int t = tid; t < cntL; t += THREADS) {
            float f = sameBin ? s_val[t] : s_val[MAXN - 1 - t];
            unsigned key = f2key(f);
            if ((key >> 14) == pL) atomicAdd(&s_hist[256 + ((key >> 6) & 0xFFu)], 1u);
        }
        __syncthreads();
        if (wid == 0) {
            unsigned b; int k2;
            resolve<256, true>(s_hist, s_kremH, lane, b, k2);
            if (lane == 0) { s_selH = (pH << 8) | b; s_kremH = k2; }
        } else if (wid == 1) {
            unsigned b; int k2;
            resolve<256, false>(s_hist + 256, s_kremL, lane, b, k2);
            if (lane == 0) { s_selL = (pL << 8) | b; s_kremL = k2; }
        }
        __syncthreads();
    }

    // ===== level 3 (bits 5..0, 64 bins) ========================================
    {
        const unsigned pH = s_selH;
        const unsigned pL = s_selL;
        if (tid < 128) { s_hist[tid] = 0; s_hist[tid + 256] = 0; }
        __syncthreads();
        for (int t = tid; t < cntH; t += THREADS) {
            unsigned key = f2key(s_val[t]);
            if ((key >> 6) == pH) atomicAdd(&s_hist[key & 0x3Fu], 1u);
        }
        for (int t = tid; t < cntL; t += THREADS) {
            float f = sameBin ? s_val[t] : s_val[MAXN - 1 - t];
            unsigned key = f2key(f);
            if ((key >> 6) == pL) atomicAdd(&s_hist[256 + (key & 0x3Fu)], 1u);
        }
        __syncthreads();
        if (wid == 0) {
            unsigned b; int k2;
            resolve<64, true>(s_hist, s_kremH, lane, b, k2);
            if (lane == 0) { s_selH = (pH << 6) | b; s_kremH = k2; }
        } else if (wid == 1) {
            unsigned b; int k2;
            resolve<64, false>(s_hist + 256, s_kremL, lane, b, k2);
            if (lane == 0) { s_selL = (pL << 6) | b; s_kremL = k2; }
        }
        __syncthreads();
    }

    const unsigned keyH = s_selH;   // full 32-bit key of kth largest
    const unsigned keyL = s_selL;   // full 32-bit key of kth smallest

    // ===== tiny final sweep over candidate values ==============================
    for (int t = tid; t < cntH; t += THREADS) {
        float f = s_val[t];
        if (f2key(f) > keyH) sumT += f;
    }
    for (int t = tid; t < cntL; t += THREADS) {
        float f = sameBin ? s_val[t] : s_val[MAXN - 1 - t];
        if (f2key(f) < keyL) sumB += f;
    }

    #pragma unroll
    for (int o = 16; o > 0; o >>= 1) {
        sumT += __shfl_xor_sync(0xFFFFFFFFu, sumT, o);
        sumB += __shfl_xor_sync(0xFFFFFFFFu, sumB, o);
    }
    if (lane == 0) { s_red[0][wid] = sumT; s_red[1][wid] = sumB; }
    __syncthreads();

    if (tid == 0) {
        float st = 0.0f, sb = 0.0f;
        #pragma unroll
        for (int w = 0; w < THREADS / 32; ++w) { st += s_red[0][w]; sb += s_red[1][w]; }
        st += (float)s_kremH * key2f(keyH);   // exact tie handling
        sb += (float)s_kremL * key2f(keyL);
        out[row] = st / (float)kmax + (alpha / (float)kmin) * sb;
    }
}

extern "C" void kernel_launch(void* const* d_in, const int* in_sizes, int n_in,
                              void* d_out, int out_size)
{
    const float* x = (const float*)d_in[0];
    float* out = (float*)d_out;

    const int rows = out_size;                 // 32*512 = 16384
    const int n = in_sizes[0] / rows;          // 4096
    int kmax = (int)lrintf(0.2f * (float)n);   // int(round(0.2*n)) = 819
    int kmin = (int)lrintf(0.2f * (float)n);
    if (kmax < 1) kmax = 1;
    if (kmin < 1) kmin = 1;

    wildcat_kernel<<<rows, THREADS>>>(x, out, n, kmax, kmin, 0.7f);
}

// round 8
// speedup vs baseline: 1.3787x; 1.3787x over previous
#include <cuda_runtime.h>
#include <math.h>

#define THREADS 256
#define MAXN 4096
#define NB1 1024        // first-pass bins (top 10 bits of key)
#define SH1 22          // 32 - 10
#define HSTRIDE 1025    // replica stride (bank-offset by 1 word)

// Order-preserving float->uint key: monotonic increasing with float value.
__device__ __forceinline__ unsigned f2key(float v) {
    unsigned u = __float_as_uint(v);
    return u ^ (unsigned)(((int)u >> 31) | 0x80000000u);
}
__device__ __forceinline__ float key2f(unsigned key) {
    unsigned u = (key & 0x80000000u) ? (key ^ 0x80000000u) : ~key;
    return __uint_as_float(u);
}

// Warp-collective: find bin containing the krem-th element (DESC = count from
// top bin downward, else from bottom upward). Returns bin index + residual rank.
// REPL=2 sums two replicas at stride HSTRIDE.
template<int NB, bool DESC, int REPL>
__device__ __forceinline__ void resolve(const unsigned* __restrict__ hist, int krem,
                                        int lane, unsigned &bin, int &krem_out)
{
    constexpr int BPL = NB / 32;
    unsigned s = 0;
    #pragma unroll
    for (int j = 0; j < BPL; j++) {
        int b = DESC ? (NB - 1 - (lane * BPL + j)) : (lane * BPL + j);
        unsigned c = hist[b];
        if (REPL == 2) c += hist[HSTRIDE + b];
        s += c;
    }
    unsigned p = s;
    #pragma unroll
    for (int o = 1; o < 32; o <<= 1) {
        unsigned t = __shfl_up_sync(0xFFFFFFFFu, p, o);
        if (lane >= o) p += t;
    }
    unsigned excl = p - s;
    bool cross = (excl < (unsigned)krem) && (p >= (unsigned)krem);
    unsigned m = __ballot_sync(0xFFFFFFFFu, cross);
    int src = __ffs(m) - 1;
    unsigned bsel = 0; int k2 = 0;
    if (lane == src) {
        unsigned cum = excl;
        #pragma unroll
        for (int j = 0; j < BPL; j++) {
            int b = DESC ? (NB - 1 - (lane * BPL + j)) : (lane * BPL + j);
            unsigned c = hist[b];
            if (REPL == 2) c += hist[HSTRIDE + b];
            if (cum + c >= (unsigned)krem) { bsel = (unsigned)b; k2 = krem - (int)cum; break; }
            cum += c;
        }
    }
    bin = __shfl_sync(0xFFFFFFFFu, bsel, src);
    krem_out = __shfl_sync(0xFFFFFFFFu, k2, src);
}

__global__ void __launch_bounds__(THREADS, 8)
wildcat_kernel(const float* __restrict__ x, float* __restrict__ out,
               int n, int kmax, int kmin, float alpha)
{
    __shared__ float    s_val[MAXN];           // candidates: H from 0, L from MAXN-1
    __shared__ unsigned s_hist[2 * HSTRIDE];   // L0: 2 replicas of 1024 bins; sublevels reuse [0:512)
    __shared__ unsigned s_selH, s_selL;
    __shared__ int      s_kremH, s_kremL;
    __shared__ int      s_cntH, s_cntL;
    __shared__ float    s_red[2][THREADS / 32];

    const int tid  = threadIdx.x;
    const int lane = tid & 31;
    const int wid  = tid >> 5;
    const long long row = blockIdx.x;
    const float* __restrict__ xr = x + row * (long long)n;

    // ---- init: clear both histogram replicas ----
    for (int b = tid; b < 2 * HSTRIDE; b += THREADS) s_hist[b] = 0;
    if (tid == 0) { s_cntH = 0; s_cntL = 0; }
    __syncthreads();

    const int n4 = n >> 2;
    const float4* __restrict__ xr4 = (const float4*)xr;
    const int nv4 = (n4 / THREADS) * THREADS;
    const int rep = (lane & 1) * HSTRIDE;      // per-lane replica base

    // ===== pass 1: gmem read + 10-bit histogram (replica-split atomics) =======
    for (int i = tid; i < nv4; i += THREADS) {
        float4 v = xr4[i];
        atomicAdd(&s_hist[rep + (f2key(v.x) >> SH1)], 1u);
        atomicAdd(&s_hist[rep + (f2key(v.y) >> SH1)], 1u);
        atomicAdd(&s_hist[rep + (f2key(v.z) >> SH1)], 1u);
        atomicAdd(&s_hist[rep + (f2key(v.w) >> SH1)], 1u);
    }
    for (int i = nv4 * 4 + tid; i < n; i += THREADS) {   // tail (none for n=4096)
        atomicAdd(&s_hist[rep + (f2key(xr[i]) >> SH1)], 1u);
    }
    __syncthreads();

    // ---- resolve level 0 (two warps in parallel; sums both replicas) ----
    if (wid == 0) {
        unsigned b; int k2;
        resolve<NB1, true, 2>(s_hist, kmax, lane, b, k2);
        if (lane == 0) { s_selH = b; s_kremH = k2; }
    } else if (wid == 1) {
        unsigned b; int k2;
        resolve<NB1, false, 2>(s_hist, kmin, lane, b, k2);
        if (lane == 0) { s_selL = b; s_kremL = k2; }
    }
    __syncthreads();

    const unsigned binH = s_selH;
    const unsigned binL = s_selL;
    const bool sameBin = (binH == binL);

    // clear the 512 sublevel bins
    s_hist[tid] = 0;
    s_hist[tid + 256] = 0;
    __syncthreads();

    // ===== pass 2: gmem re-read (L2/L1 hit): bulk sums + per-quad batched
    //        compaction + inline level-1 (bits 21..14) histograms ==============
    float sumT = 0.0f, sumB = 0.0f;
    for (int i = tid; i < nv4; i += THREADS) {
        float4 v = xr4[i];
        unsigned k0 = f2key(v.x), k1 = f2key(v.y), k2_ = f2key(v.z), k3 = f2key(v.w);
        unsigned b0 = k0 >> SH1, b1 = k1 >> SH1, b2 = k2_ >> SH1, b3 = k3 >> SH1;
        if (b0 > binH) sumT += v.x;
        if (b1 > binH) sumT += v.y;
        if (b2 > binH) sumT += v.z;
        if (b3 > binH) sumT += v.w;
        if (b0 < binL) sumB += v.x;
        if (b1 < binL) sumB += v.y;
        if (b2 < binL) sumB += v.z;
        if (b3 < binL) sumB += v.w;

        int cH = (b0 == binH) + (b1 == binH) + (b2 == binH) + (b3 == binH);
        if (cH) {
            int p = atomicAdd(&s_cntH, cH);
            if (b0 == binH) { s_val[p++] = v.x; atomicAdd(&s_hist[(k0 >> 14) & 0xFFu], 1u); }
            if (b1 == binH) { s_val[p++] = v.y; atomicAdd(&s_hist[(k1 >> 14) & 0xFFu], 1u); }
            if (b2 == binH) { s_val[p++] = v.z; atomicAdd(&s_hist[(k2_ >> 14) & 0xFFu], 1u); }
            if (b3 == binH) { s_val[p++] = v.w; atomicAdd(&s_hist[(k3 >> 14) & 0xFFu], 1u); }
        }
        if (!sameBin) {
            int cL = (b0 == binL) + (b1 == binL) + (b2 == binL) + (b3 == binL);
            if (cL) {
                int p = atomicAdd(&s_cntL, cL);
                if (b0 == binL) { s_val[MAXN - 1 - p++] = v.x; atomicAdd(&s_hist[256 + ((k0 >> 14) & 0xFFu)], 1u); }
                if (b1 == binL) { s_val[MAXN - 1 - p++] = v.y; atomicAdd(&s_hist[256 + ((k1 >> 14) & 0xFFu)], 1u); }
                if (b2 == binL) { s_val[MAXN - 1 - p++] = v.z; atomicAdd(&s_hist[256 + ((k2_ >> 14) & 0xFFu)], 1u); }
                if (b3 == binL) { s_val[MAXN - 1 - p++] = v.w; atomicAdd(&s_hist[256 + ((k3 >> 14) & 0xFFu)], 1u); }
            }
        }
    }
    for (int i = nv4 * 4 + tid; i < n; i += THREADS) {   // tail
        float f = xr[i];
        unsigned key = f2key(f);
        unsigned b = key >> SH1;
        if (b > binH) sumT += f;
        if (b < binL) sumB += f;
        if (b == binH) {
            int p = atomicAdd(&s_cntH, 1);
            s_val[p] = f;
            atomicAdd(&s_hist[(key >> 14) & 0xFFu], 1u);
        } else if (b == binL) {
            int p = atomicAdd(&s_cntL, 1);
            s_val[MAXN - 1 - p] = f;
            atomicAdd(&s_hist[256 + ((key >> 14) & 0xFFu)], 1u);
        }
    }
    __syncthreads();

    const int cntH = s_cntH;
    const int cntL = sameBin ? cntH : s_cntL;

    // ---- resolve level 1 (bits 21..14) ----
    if (wid == 0) {
        unsigned b; int k2;
        resolve<256, true, 1>(s_hist, s_kremH, lane, b, k2);
        if (lane == 0) { s_selH = (binH << 8) | b; s_kremH = k2; }
    } else if (wid == 1) {
        unsigned b; int k2;
        resolve<256, false, 1>(sameBin ? s_hist : (s_hist + 256), s_kremL, lane, b, k2);
        if (lane == 0) { s_selL = (binL << 8) | b; s_kremL = k2; }
    }
    __syncthreads();

    // ===== level 2 (bits 13..6) over candidate values ==========================
    {
        const unsigned pH = s_selH;
        const unsigned pL = s_selL;
        s_hist[tid] = 0;
        s_hist[tid + 256] = 0;
        __syncthreads();
        for (int t = tid; t < cntH; t += THREADS) {
            unsigned key = f2key(s_val[t]);
            if ((key >> 14) == pH) atomicAdd(&s_hist[(key >> 6) & 0xFFu], 1u);
        }
        for (int t = tid; t < cntL; t += THREADS) {
            float f = sameBin ? s_val[t] : s_val[MAXN - 1 - t];
            unsigned key = f2key(f);
            if ((key >> 14) == pL) atomicAdd(&s_hist[256 + ((key >> 6) & 0xFFu)], 1u);
        }
        __syncthreads();
        if (wid == 0) {
            unsigned b; int k2;
            resolve<256, true, 1>(s_hist, s_kremH, lane, b, k2);
            if (lane == 0) { s_selH = (pH << 8) | b; s_kremH = k2; }
        } else if (wid == 1) {
            unsigned b; int k2;
            resolve<256, false, 1>(s_hist + 256, s_kremL, lane, b, k2);
            if (lane == 0) { s_selL = (pL << 8) | b; s_kremL = k2; }
        }
        __syncthreads();
    }

    // ===== level 3 (bits 5..0, 64 bins) ========================================
    {
        const unsigned pH = s_selH;
        const unsigned pL = s_selL;
        if (tid < 128) { s_hist[tid] = 0; s_hist[tid + 256] = 0; }
        __syncthreads();
        for (int t = tid; t < cntH; t += THREADS) {
            unsigned key = f2key(s_val[t]);
            if ((key >> 6) == pH) atomicAdd(&s_hist[key & 0x3Fu], 1u);
        }
        for (int t = tid; t < cntL; t += THREADS) {
            float f = sameBin ? s_val[t] : s_val[MAXN - 1 - t];
            unsigned key = f2key(f);
            if ((key >> 6) == pL) atomicAdd(&s_hist[256 + (key & 0x3Fu)], 1u);
        }
        __syncthreads();
        if (wid == 0) {
            unsigned b; int k2;
            resolve<64, true, 1>(s_hist, s_kremH, lane, b, k2);
            if (lane == 0) { s_selH = (pH << 6) | b; s_kremH = k2; }
        } else if (wid == 1) {
            unsigned b; int k2;
            resolve<64, false, 1>(s_hist + 256, s_kremL, lane, b, k2);
            if (lane == 0) { s_selL = (pL << 6) | b; s_kremL = k2; }
        }
        __syncthreads();
    }

    const unsigned keyH = s_selH;   // full 32-bit key of kth largest
    const unsigned keyL = s_selL;   // full 32-bit key of kth smallest

    // ===== tiny final sweep over candidate values ==============================
    for (int t = tid; t < cntH; t += THREADS) {
        float f = s_val[t];
        if (f2key(f) > keyH) sumT += f;
    }
    for (int t = tid; t < cntL; t += THREADS) {
        float f = sameBin ? s_val[t] : s_val[MAXN - 1 - t];
        if (f2key(f) < keyL) sumB += f;
    }

    #pragma unroll
    for (int o = 16; o > 0; o >>= 1) {
        sumT += __shfl_xor_sync(0xFFFFFFFFu, sumT, o);
        sumB += __shfl_xor_sync(0xFFFFFFFFu, sumB, o);
    }
    if (lane == 0) { s_red[0][wid] = sumT; s_red[1][wid] = sumB; }
    __syncthreads();

    if (tid == 0) {
        float st = 0.0f, sb = 0.0f;
        #pragma unroll
        for (int w = 0; w < THREADS / 32; ++w) { st += s_red[0][w]; sb += s_red[1][w]; }
        st += (float)s_kremH * key2f(keyH);   // exact tie handling
        sb += (float)s_kremL * key2f(keyL);
        out[row] = st / (float)kmax + (alpha / (float)kmin) * sb;
    }
}

extern "C" void kernel_launch(void* const* d_in, const int* in_sizes, int n_in,
                              void* d_out, int out_size)
{
    const float* x = (const float*)d_in[0];
    float* out = (float*)d_out;

    const int rows = out_size;                 // 32*512 = 16384
    const int n = in_sizes[0] / rows;          // 4096
    int kmax = (int)lrintf(0.2f * (float)n);   // int(round(0.2*n)) = 819
    int kmin = (int)lrintf(0.2f * (float)n);
    if (kmax < 1) kmax = 1;
    if (kmin < 1) kmin = 1;

    wildcat_kernel<<<rows, THREADS>>>(x, out, n, kmax, kmin, 0.7f);
}

// round 9
// speedup vs baseline: 1.7355x; 1.2588x over previous
#include <cuda_runtime.h>
#include <math.h>

#define THREADS 256
#define MAXN 4096
#define NB0 4096        // level-0 bins (top 12 bits of key)
#define SH0 20          // 32 - 12

// Order-preserving float->uint key: monotonic increasing with float value.
__device__ __forceinline__ unsigned f2key(float v) {
    unsigned u = __float_as_uint(v);
    return u ^ (unsigned)(((int)u >> 31) | 0x80000000u);
}
__device__ __forceinline__ float key2f(unsigned key) {
    unsigned u = (key & 0x80000000u) ? (key ^ 0x80000000u) : ~key;
    return __uint_as_float(u);
}

// Warp-collective small resolve (NB in {64,256}): find bin containing the
// krem-th element (DESC = count from top bin down). Returns bin + residual rank.
template<int NB, bool DESC>
__device__ __forceinline__ void resolve_small(const unsigned* __restrict__ hist, int krem,
                                              int lane, unsigned &bin, int &krem_out)
{
    constexpr int BPL = NB / 32;
    unsigned s = 0;
    #pragma unroll
    for (int j = 0; j < BPL; j++) {
        int b = DESC ? (NB - 1 - (lane * BPL + j)) : (lane * BPL + j);
        s += hist[b];
    }
    unsigned p = s;
    #pragma unroll
    for (int o = 1; o < 32; o <<= 1) {
        unsigned t = __shfl_up_sync(0xFFFFFFFFu, p, o);
        if (lane >= o) p += t;
    }
    unsigned excl = p - s;
    bool cross = (excl < (unsigned)krem) && (p >= (unsigned)krem);
    unsigned m = __ballot_sync(0xFFFFFFFFu, cross);
    int src = __ffs(m) - 1;
    unsigned bsel = 0; int k2 = 0;
    if (lane == src) {
        unsigned cum = excl;
        #pragma unroll
        for (int j = 0; j < BPL; j++) {
            int b = DESC ? (NB - 1 - (lane * BPL + j)) : (lane * BPL + j);
            unsigned c = hist[b];
            if (cum + c >= (unsigned)krem) { bsel = (unsigned)b; k2 = krem - (int)cum; break; }
            cum += c;
        }
    }
    bin = __shfl_sync(0xFFFFFFFFu, bsel, src);
    krem_out = __shfl_sync(0xFFFFFFFFu, k2, src);
}

// Warp-collective resolve over 4096 bins; lane owns bins [128*lane, 128*lane+128),
// summed with uint4 loads.
template<bool DESC>
__device__ __forceinline__ void resolve_big(const unsigned* __restrict__ hist, int krem,
                                            int lane, unsigned &bin, int &krem_out)
{
    const uint4* h4 = (const uint4*)hist;
    unsigned s = 0;
    #pragma unroll
    for (int j = 0; j < 32; j++) {
        uint4 c = h4[lane * 32 + j];
        s += c.x + c.y + c.z + c.w;
    }
    unsigned p = s;
    if (DESC) {     // cumulative from highest bins downward = suffix scan over lanes
        #pragma unroll
        for (int o = 1; o < 32; o <<= 1) {
            unsigned t = __shfl_down_sync(0xFFFFFFFFu, p, o);
            if (lane + o < 32) p += t;
        }
    } else {        // prefix scan over lanes
        #pragma unroll
        for (int o = 1; o < 32; o <<= 1) {
            unsigned t = __shfl_up_sync(0xFFFFFFFFu, p, o);
            if (lane >= o) p += t;
        }
    }
    unsigned excl = p - s;
    bool cross = (excl < (unsigned)krem) && (p >= (unsigned)krem);
    unsigned m = __ballot_sync(0xFFFFFFFFu, cross);
    int src = __ffs(m) - 1;
    unsigned bsel = 0; int k2 = 0;
    if (cross) {
        unsigned cum = excl;
        if (DESC) {
            for (int b = lane * 128 + 127; b >= lane * 128; --b) {
                unsigned c = hist[b];
                if (cum + c >= (unsigned)krem) { bsel = (unsigned)b; k2 = krem - (int)cum; break; }
                cum += c;
            }
        } else {
            for (int b = lane * 128; b < lane * 128 + 128; ++b) {
                unsigned c = hist[b];
                if (cum + c >= (unsigned)krem) { bsel = (unsigned)b; k2 = krem - (int)cum; break; }
                cum += c;
            }
        }
    }
    bin = __shfl_sync(0xFFFFFFFFu, bsel, src);
    krem_out = __shfl_sync(0xFFFFFFFFu, k2, src);
}

__global__ void __launch_bounds__(THREADS, 8)
wildcat_kernel(const float* __restrict__ x, float* __restrict__ out,
               int n, int kmax, int kmin, float alpha)
{
    // s_hist0 (16 KB) is dead after level-0 resolve; candidate values overlay it.
    __shared__ unsigned s_hist0[NB0];
    __shared__ unsigned s_subh[512];       // sublevel hists: [0:256)=H, [256:512)=L
    __shared__ unsigned s_selH, s_selL;
    __shared__ int      s_kremH, s_kremL;
    __shared__ int      s_cntH, s_cntL;
    __shared__ float    s_red[2][THREADS / 32];
    float* s_val = (float*)s_hist0;        // overlay: H grows from 0, L from MAXN-1

    const int tid  = threadIdx.x;
    const int lane = tid & 31;
    const int wid  = tid >> 5;
    const long long row = blockIdx.x;
    const float* __restrict__ xr = x + row * (long long)n;

    // ---- init: clear level-0 histogram (uint4 stores) ----
    {
        uint4 z = make_uint4(0, 0, 0, 0);
        uint4* h4 = (uint4*)s_hist0;
        h4[tid] = z; h4[tid + 256] = z; h4[tid + 512] = z; h4[tid + 768] = z;
    }
    if (tid == 0) { s_cntH = 0; s_cntL = 0; }
    __syncthreads();

    const int n4 = n >> 2;
    const float4* __restrict__ xr4 = (const float4*)xr;
    const int nv4 = (n4 / THREADS) * THREADS;

    // ===== pass 1: gmem read + 12-bit histogram (low-conflict spread bins) ====
    for (int i = tid; i < nv4; i += THREADS) {
        float4 v = xr4[i];
        atomicAdd(&s_hist0[f2key(v.x) >> SH0], 1u);
        atomicAdd(&s_hist0[f2key(v.y) >> SH0], 1u);
        atomicAdd(&s_hist0[f2key(v.z) >> SH0], 1u);
        atomicAdd(&s_hist0[f2key(v.w) >> SH0], 1u);
    }
    for (int i = nv4 * 4 + tid; i < n; i += THREADS) {   // tail (none for n=4096)
        atomicAdd(&s_hist0[f2key(xr[i]) >> SH0], 1u);
    }
    __syncthreads();

    // ---- resolve level 0 (two warps in parallel) ----
    if (wid == 0) {
        unsigned b; int k2;
        resolve_big<true>(s_hist0, kmax, lane, b, k2);
        if (lane == 0) { s_selH = b; s_kremH = k2; }
    } else if (wid == 1) {
        unsigned b; int k2;
        resolve_big<false>(s_hist0, kmin, lane, b, k2);
        if (lane == 0) { s_selL = b; s_kremL = k2; }
    }
    // clear sublevel hists while warps 0/1 resolve
    if (tid < 256) { s_subh[tid] = 0; s_subh[tid + 256] = 0; }
    __syncthreads();

    const unsigned binH = s_selH;
    const unsigned binL = s_selL;
    const bool sameBin = (binH == binL);
    __syncthreads();   // all reads of s_hist0 complete before s_val overlay writes

    // ===== pass 2: gmem re-read (cache hit): bulk sums + value compaction ======
    float sumT = 0.0f, sumB = 0.0f;
    for (int i = tid; i < nv4; i += THREADS) {
        float4 v = xr4[i];
        #pragma unroll
        for (int j = 0; j < 4; j++) {
            float f = (j == 0) ? v.x : (j == 1) ? v.y : (j == 2) ? v.z : v.w;
            unsigned b = f2key(f) >> SH0;
            if (b > binH) sumT += f;
            if (b < binL) sumB += f;
            if (b == binH) {
                int p = atomicAdd(&s_cntH, 1);
                s_val[p] = f;
            } else if (b == binL) {            // implies !sameBin
                int p = atomicAdd(&s_cntL, 1);
                s_val[MAXN - 1 - p] = f;
            }
        }
    }
    for (int i = nv4 * 4 + tid; i < n; i += THREADS) {   // tail
        float f = xr[i];
        unsigned b = f2key(f) >> SH0;
        if (b > binH) sumT += f;
        if (b < binL) sumB += f;
        if (b == binH) {
            int p = atomicAdd(&s_cntH, 1);
            s_val[p] = f;
        } else if (b == binL) {
            int p = atomicAdd(&s_cntL, 1);
            s_val[MAXN - 1 - p] = f;
        }
    }
    __syncthreads();

    const int cntH = s_cntH;
    const int cntL = sameBin ? cntH : s_cntL;

    // ===== level 1 (bits 19..12): no filter needed — lists are bin-pure =======
    for (int t = tid; t < cntH; t += THREADS)
        atomicAdd(&s_subh[(f2key(s_val[t]) >> 12) & 0xFFu], 1u);
    if (!sameBin)
        for (int t = tid; t < cntL; t += THREADS)
            atomicAdd(&s_subh[256 + ((f2key(s_val[MAXN - 1 - t]) >> 12) & 0xFFu)], 1u);
    __syncthreads();

    if (wid == 0) {
        unsigned b; int k2;
        resolve_small<256, true>(s_subh, s_kremH, lane, b, k2);
        if (lane == 0) { s_selH = (binH << 8) | b; s_kremH = k2; }
    } else if (wid == 1) {
        unsigned b; int k2;
        resolve_small<256, false>(sameBin ? s_subh : (s_subh + 256), s_kremL, lane, b, k2);
        if (lane == 0) { s_selL = (binL << 8) | b; s_kremL = k2; }
    }
    __syncthreads();

    // ===== level 2 (bits 11..6, 64 bins) =======================================
    {
        const unsigned pH = s_selH;     // 20-bit prefix
        const unsigned pL = s_selL;
        if (tid < 64)  { s_subh[tid] = 0; s_subh[tid + 256] = 0; }
        __syncthreads();
        for (int t = tid; t < cntH; t += THREADS) {
            unsigned key = f2key(s_val[t]);
            if ((key >> 12) == pH) atomicAdd(&s_subh[(key >> 6) & 0x3Fu], 1u);
        }
        for (int t = tid; t < cntL; t += THREADS) {
            float f = sameBin ? s_val[t] : s_val[MAXN - 1 - t];
            unsigned key = f2key(f);
            if ((key >> 12) == pL) atomicAdd(&s_subh[256 + ((key >> 6) & 0x3Fu)], 1u);
        }
        __syncthreads();
        if (wid == 0) {
            unsigned b; int k2;
            resolve_small<64, true>(s_subh, s_kremH, lane, b, k2);
            if (lane == 0) { s_selH = (pH << 6) | b; s_kremH = k2; }
        } else if (wid == 1) {
            unsigned b; int k2;
            resolve_small<64, false>(s_subh + 256, s_kremL, lane, b, k2);
            if (lane == 0) { s_selL = (pL << 6) | b; s_kremL = k2; }
        }
        __syncthreads();
    }

    // ===== level 3 (bits 5..0, 64 bins) ========================================
    {
        const unsigned pH = s_selH;     // 26-bit prefix
        const unsigned pL = s_selL;
        if (tid < 64)  { s_subh[tid] = 0; s_subh[tid + 256] = 0; }
        __syncthreads();
        for (int t = tid; t < cntH; t += THREADS) {
            unsigned key = f2key(s_val[t]);
            if ((key >> 6) == pH) atomicAdd(&s_subh[key & 0x3Fu], 1u);
        }
        for (int t = tid; t < cntL; t += THREADS) {
            float f = sameBin ? s_val[t] : s_val[MAXN - 1 - t];
            unsigned key = f2key(f);
            if ((key >> 6) == pL) atomicAdd(&s_subh[256 + (key & 0x3Fu)], 1u);
        }
        __syncthreads();
        if (wid == 0) {
            unsigned b; int k2;
            resolve_small<64, true>(s_subh, s_kremH, lane, b, k2);
            if (lane == 0) { s_selH = (pH << 6) | b; s_kremH = k2; }
        } else if (wid == 1) {
            unsigned b; int k2;
            resolve_small<64, false>(s_subh + 256, s_kremL, lane, b, k2);
            if (lane == 0) { s_selL = (pL << 6) | b; s_kremL = k2; }
        }
        __syncthreads();
    }

    const unsigned keyH = s_selH;   // full 32-bit key of kth largest
    const unsigned keyL = s_selL;   // full 32-bit key of kth smallest

    // ===== tiny final sweep over candidate values ==============================
    for (int t = tid; t < cntH; t += THREADS) {
        float f = s_val[t];
        if (f2key(f) > keyH) sumT += f;
    }
    for (int t = tid; t < cntL; t += THREADS) {
        float f = sameBin ? s_val[t] : s_val[MAXN - 1 - t];
        if (f2key(f) < keyL) sumB += f;
    }

    #pragma unroll
    for (int o = 16; o > 0; o >>= 1) {
        sumT += __shfl_xor_sync(0xFFFFFFFFu, sumT, o);
        sumB += __shfl_xor_sync(0xFFFFFFFFu, sumB, o);
    }
    if (lane == 0) { s_red[0][wid] = sumT; s_red[1][wid] = sumB; }
    __syncthreads();

    if (tid == 0) {
        float st = 0.0f, sb = 0.0f;
        #pragma unroll
        for (int w = 0; w < THREADS / 32; ++w) { st += s_red[0][w]; sb += s_red[1][w]; }
        st += (float)s_kremH * key2f(keyH);   // exact tie handling
        sb += (float)s_kremL * key2f(keyL);
        out[row] = st / (float)kmax + (alpha / (float)kmin) * sb;
    }
}

extern "C" void kernel_launch(void* const* d_in, const int* in_sizes, int n_in,
                              void* d_out, int out_size)
{
    const float* x = (const float*)d_in[0];
    float* out = (float*)d_out;

    const int rows = out_size;                 // 32*512 = 16384
    const int n = in_sizes[0] / rows;          // 4096
    int kmax = (int)lrintf(0.2f * (float)n);   // int(round(0.2*n)) = 819
    int kmin = (int)lrintf(0.2f * (float)n);
    if (kmax < 1) kmax = 1;
    if (kmin < 1) kmin = 1;

    wildcat_kernel<<<rows, THREADS>>>(x, out, n, kmax, kmin, 0.7f);
}